// round 16
// baseline (speedup 1.0000x reference)
#include <cuda_runtime.h>
#include <cstdint>

#define NCLS   10
#define NB     32
#define NBINS  (NB * NCLS)      // 320
#define NAT    512
#define DIN    272
#define HID    64
#define NOUT   128
#define L0OUT  256
#define IN0    32
#define NT     384
#define NW     12               // warps per block
#define NPAIR  6                // warp pairs per block

__device__ __forceinline__ float silu_f(float x) {
    return x * (1.0f / (1.0f + __expf(-x)));
}

// packed dual-fp32 FMA: d.lo += a.lo*b.lo ; d.hi += a.hi*b.hi
__device__ __forceinline__ void ffma2(unsigned long long& d,
                                      unsigned long long a,
                                      unsigned long long b) {
    asm("fma.rn.f32x2 %0, %1, %2, %0;" : "+l"(d) : "l"(a), "l"(b));
}
__device__ __forceinline__ unsigned long long pack2(float x) {
    unsigned long long r;
    asm("mov.b64 %0, {%1, %1};" : "=l"(r) : "f"(x));
    return r;
}
__device__ __forceinline__ float lo32(unsigned long long v) {
    return __uint_as_float((unsigned)(v & 0xffffffffull));
}
__device__ __forceinline__ float hi32(unsigned long long v) {
    return __uint_as_float((unsigned)(v >> 32));
}
__device__ __forceinline__ void pair_bar(int id) {
    asm volatile("bar.sync %0, %1;" :: "r"(id), "r"(64) : "memory");
}

// ===========================================================================
// Pair-split warp-autonomous kernel. Block = (b, cls), 12 warps = 6 pairs.
// Pair p owns groups {p, p+6, ...} of 8 atoms; within a pair each warp owns
// a 32-output half (lane = one output). Pair-scoped named barriers; block
// barriers only at prologue and merge. Stateless, no atomics.
// ===========================================================================
__global__ __launch_bounds__(NT, 3) void fused_kernel(
    const float* __restrict__ af,      // (16384, 272)
    const float* __restrict__ W0,      // (T, 32, 256)
    const float* __restrict__ W1,      // (T, 64, 256)
    const float* __restrict__ Wo,      // (T, 64, 128)
    const int*   __restrict__ mapping, // (16384)
    float*       __restrict__ out)     // (NB, T*128)
{
    __shared__ float WaN[IN0 * HID];        // [k][o] natural        8KB
    __shared__ float WbN[HID * HID];        // [k][o] natural       16KB
    __shared__ float xw[NPAIR][IN0 * 8];    // per-pair x  [k][a]    6KB
    __shared__ float sw[NPAIR][HID * 8];    // per-pair s1 [o][a]   12KB
    __shared__ float pw[NPAIR * HID];       // pair partials        1.5KB
    __shared__ float red[HID];
    __shared__ float psum[2 * NOUT];
    __shared__ int   list_s[NAT];           // compacted atom idx    2KB
    __shared__ int   wcnt[17];

    const int t    = threadIdx.x;
    const int w    = t >> 5;
    const int lane = t & 31;
    const int p    = t >> 6;               // pair 0..5
    const int u    = t & 63;               // tid within pair
    const int bin  = blockIdx.x;
    const int b    = bin / NCLS;
    const int cls  = bin % NCLS;

    // ---------------- prologue ----------------
    const int m0 = mapping[b * NAT + t];                      // atoms 0..383
    const int m1 = (t < 128) ? mapping[b * NAT + 384 + t] : -1;

    // stage weights (live 64 of 256 cols), strided loops
    {
        const float4* w0p = (const float4*)(W0 + (size_t)cls * IN0 * L0OUT);
        #pragma unroll
        for (int idx = 0; idx < 512; idx += NT) {
            int i = idx + t;
            if (i < 512)
                ((float4*)WaN)[(i >> 4) * 16 + (i & 15)] =
                    __ldg(&w0p[(i >> 4) * 64 + (i & 15)]);
        }
        const float4* w1p = (const float4*)(W1 + (size_t)cls * HID * L0OUT);
        #pragma unroll
        for (int idx = 0; idx < 1024; idx += NT) {
            int i = idx + t;
            if (i < 1024)
                ((float4*)WbN)[(i >> 4) * 16 + (i & 15)] =
                    __ldg(&w1p[(i >> 4) * 64 + (i & 15)]);
        }
    }

    // deterministic compaction (ascending atom index order)
    const unsigned lmask = (1u << lane) - 1u;
    unsigned mk0 = __ballot_sync(0xffffffffu, m0 == cls);
    unsigned mk1 = __ballot_sync(0xffffffffu, m1 == cls);
    if (lane == 0) {
        wcnt[w] = __popc(mk0);
        if (w < 4) wcnt[12 + w] = __popc(mk1);
    }
    __syncthreads();
    if (t == 0) {
        int s = 0;
        #pragma unroll
        for (int i = 0; i < 16; i++) { int c = wcnt[i]; wcnt[i] = s; s += c; }
        wcnt[16] = s;
    }
    __syncthreads();
    const int cnt = wcnt[16];
    if (m0 == cls) list_s[wcnt[w] + __popc(mk0 & lmask)] = t;
    if (t < 128 && m1 == cls)
        list_s[wcnt[12 + w] + __popc(mk1 & lmask)] = 384 + t;
    __syncthreads();        // list + weights visible (one block barrier)

    // =================== pair-autonomous mainloop ===========================
    const int ngroups = (cnt + 7) >> 3;
    const int o       = (w & 1) * 32 + lane;   // this warp's output
    const int barid   = 1 + p;
    const float RS32  = 0.17677669529663687f;  // 1/sqrt(32)
    float part = 0.f;
    float* xwp = xw[p];
    float* swp = sw[p];

    for (int g = p; g < ngroups; g += NPAIR) {
        // ---- pair-wide gather: 8 atoms x 32 features, [k][a] ----
        {
            int a = u >> 3;                // atom slot 0..7
            int h = u & 7;                 // feature quarter (4 floats)
            int i = g * 8 + a;
            float4 r;
            if (i < cnt) {
                int id = b * NAT + list_s[i];
                r = __ldg((const float4*)(af + (size_t)id * DIN + h * 4));
            } else {
                r = make_float4(0.f, 0.f, 0.f, 0.f);
            }
            int kb = h * 4;
            xwp[(kb + 0) * 8 + a] = r.x;
            xwp[(kb + 1) * 8 + a] = r.y;
            xwp[(kb + 2) * 8 + a] = r.z;
            xwp[(kb + 3) * 8 + a] = r.w;
        }
        pair_bar(barid);

        // ---- stage 1: [8a x 32k] for output o ----
        unsigned long long acc[4];
        #pragma unroll
        for (int q = 0; q < 4; q++) acc[q] = 0ull;
        #pragma unroll
        for (int k = 0; k < IN0; k++) {
            ulonglong2 u0 = *(const ulonglong2*)&xwp[k * 8];      // broadcast
            ulonglong2 u1 = *(const ulonglong2*)&xwp[k * 8 + 4];
            unsigned long long wd = pack2(WaN[k * HID + o]);
            ffma2(acc[0], u0.x, wd);
            ffma2(acc[1], u0.y, wd);
            ffma2(acc[2], u1.x, wd);
            ffma2(acc[3], u1.y, wd);
        }
        // silu + store row o (8 atoms): 2 STS.128
        {
            float4 v0, v1;
            v0.x = silu_f(lo32(acc[0]) * RS32);
            v0.y = silu_f(hi32(acc[0]) * RS32);
            v0.z = silu_f(lo32(acc[1]) * RS32);
            v0.w = silu_f(hi32(acc[1]) * RS32);
            v1.x = silu_f(lo32(acc[2]) * RS32);
            v1.y = silu_f(hi32(acc[2]) * RS32);
            v1.z = silu_f(lo32(acc[3]) * RS32);
            v1.w = silu_f(hi32(acc[3]) * RS32);
            *(float4*)&swp[o * 8]     = v0;
            *(float4*)&swp[o * 8 + 4] = v1;
        }
        pair_bar(barid);

        // ---- stage 2: [8a x 64k] for output o; pads are exact zeros ----
        unsigned long long acc2[4];
        #pragma unroll
        for (int q = 0; q < 4; q++) acc2[q] = 0ull;
        #pragma unroll
        for (int k = 0; k < HID; k++) {
            ulonglong2 u0 = *(const ulonglong2*)&swp[k * 8];      // broadcast
            ulonglong2 u1 = *(const ulonglong2*)&swp[k * 8 + 4];
            unsigned long long wd = pack2(WbN[k * HID + o]);
            ffma2(acc2[0], u0.x, wd);
            ffma2(acc2[1], u0.y, wd);
            ffma2(acc2[2], u1.x, wd);
            ffma2(acc2[3], u1.y, wd);
        }
        #pragma unroll
        for (int q = 0; q < 4; q++)
            part += silu_f(lo32(acc2[q]) * 0.125f)
                  + silu_f(hi32(acc2[q]) * 0.125f);
        pair_bar(barid);       // sw/xw reused next group
    }

    // ---- merge pair partials ----
    pw[p * HID + o] = part;    // both warps of pair write disjoint o
    __syncthreads();
    if (t < HID) {
        float s = 0.f;
        #pragma unroll
        for (int j = 0; j < NPAIR; j++) s += pw[j * HID + t];
        red[t] = s;
    }
    __syncthreads();

    // ===== epilogue: out = (red @ Wout[cls]) / 8, 2-way k-split =====
    if (t < 2 * NOUT) {
        int oo = t & 127, half = t >> 7;
        const float* wp = Wo + (size_t)cls * HID * NOUT + half * 32 * NOUT + oo;
        float s = 0.0f;
        #pragma unroll
        for (int h = 0; h < 32; h++)
            s += red[half * 32 + h] * __ldg(&wp[h * NOUT]);
        psum[t] = s;
    }
    __syncthreads();
    if (t < NOUT)
        out[b * (NCLS * NOUT) + cls * NOUT + t] =
            0.125f * (psum[t] + psum[NOUT + t]);
}

// ---------------------------------------------------------------------------
extern "C" void kernel_launch(void* const* d_in, const int* in_sizes, int n_in,
                              void* d_out, int out_size) {
    const float* af      = (const float*)d_in[0];   // atom_features
    const float* W0      = (const float*)d_in[1];   // W0_0
    const float* W1      = (const float*)d_in[5];   // W1_0
    const float* Wo      = (const float*)d_in[9];   // Wout
    const int*   mapping = (const int*)  d_in[10];  // mlp_mapping
    float* out = (float*)d_out;

    fused_kernel<<<NBINS, NT>>>(af, W0, W1, Wo, mapping, out);
}

// round 17
// speedup vs baseline: 1.2388x; 1.2388x over previous
#include <cuda_runtime.h>
#include <cstdint>

#define NCLS   10
#define NB     32
#define NBINS  (NB * NCLS)      // 320
#define NAT    512
#define DIN    272
#define HID    64
#define NOUT   128
#define L0OUT  256
#define IN0    32
#define NT     384
#define NW     12               // warps per block

__device__ __forceinline__ float silu_f(float x) {
    return x * (1.0f / (1.0f + __expf(-x)));
}

// packed dual-fp32 FMA: d.lo += a.lo*b.lo ; d.hi += a.hi*b.hi
__device__ __forceinline__ void ffma2(unsigned long long& d,
                                      unsigned long long a,
                                      unsigned long long b) {
    asm("fma.rn.f32x2 %0, %1, %2, %0;" : "+l"(d) : "l"(a), "l"(b));
}
__device__ __forceinline__ unsigned long long pack2(float x) {
    unsigned long long r;
    asm("mov.b64 %0, {%1, %1};" : "=l"(r) : "f"(x));
    return r;
}
__device__ __forceinline__ float lo32(unsigned long long v) {
    return __uint_as_float((unsigned)(v & 0xffffffffull));
}
__device__ __forceinline__ float hi32(unsigned long long v) {
    return __uint_as_float((unsigned)(v >> 32));
}

// ===========================================================================
// Warp-autonomous kernel, 4-atom groups. Block = (b, cls), 12 warps.
// Warp w owns groups {w, w+12, ...}; each group = 4 atoms, lane owns outputs
// (2*lane, 2*lane+1). Gather + both stages are warp-private (__syncwarp only).
// Block barriers only at prologue and merge. Stateless, no atomics.
// ===========================================================================
__global__ __launch_bounds__(NT, 3) void fused_kernel(
    const float* __restrict__ af,      // (16384, 272)
    const float* __restrict__ W0,      // (T, 32, 256)
    const float* __restrict__ W1,      // (T, 64, 256)
    const float* __restrict__ Wo,      // (T, 64, 128)
    const int*   __restrict__ mapping, // (16384)
    float*       __restrict__ out)     // (NB, T*128)
{
    __shared__ float WaN[IN0 * HID];      // [k][o] natural        8KB
    __shared__ float WbN[HID * HID];      // [k][o] natural       16KB
    __shared__ float xw[NW][IN0 * 4];     // per-warp x  [k][a]    6KB
    __shared__ float sw[NW][HID * 4];     // per-warp s1 [o][a]   12KB
    __shared__ float pw[NW * HID];        // warp partials         3KB
    __shared__ float red[HID];
    __shared__ float psum[2 * NOUT];
    __shared__ int   list_s[NAT];         // compacted atom idx    2KB
    __shared__ int   wcnt[17];

    const int t    = threadIdx.x;
    const int w    = t >> 5;
    const int lane = t & 31;
    const int bin  = blockIdx.x;
    const int b    = bin / NCLS;
    const int cls  = bin % NCLS;

    // ---------------- prologue ----------------
    const int m0 = mapping[b * NAT + t];                      // atoms 0..383
    const int m1 = (t < 128) ? mapping[b * NAT + 384 + t] : -1;

    // stage weights (live 64 of 256 cols)
    {
        const float4* w0p = (const float4*)(W0 + (size_t)cls * IN0 * L0OUT);
        #pragma unroll
        for (int idx = 0; idx < 512; idx += NT) {
            int i = idx + t;
            if (i < 512)
                ((float4*)WaN)[(i >> 4) * 16 + (i & 15)] =
                    __ldg(&w0p[(i >> 4) * 64 + (i & 15)]);
        }
        const float4* w1p = (const float4*)(W1 + (size_t)cls * HID * L0OUT);
        #pragma unroll
        for (int idx = 0; idx < 1024; idx += NT) {
            int i = idx + t;
            if (i < 1024)
                ((float4*)WbN)[(i >> 4) * 16 + (i & 15)] =
                    __ldg(&w1p[(i >> 4) * 64 + (i & 15)]);
        }
    }

    // deterministic compaction (ascending atom index order)
    const unsigned lmask = (1u << lane) - 1u;
    unsigned mk0 = __ballot_sync(0xffffffffu, m0 == cls);
    unsigned mk1 = __ballot_sync(0xffffffffu, m1 == cls);
    if (lane == 0) {
        wcnt[w] = __popc(mk0);
        if (w < 4) wcnt[12 + w] = __popc(mk1);
    }
    __syncthreads();
    if (t == 0) {
        int s = 0;
        #pragma unroll
        for (int i = 0; i < 16; i++) { int c = wcnt[i]; wcnt[i] = s; s += c; }
        wcnt[16] = s;
    }
    __syncthreads();
    const int cnt = wcnt[16];
    if (m0 == cls) list_s[wcnt[w] + __popc(mk0 & lmask)] = t;
    if (t < 128 && m1 == cls)
        list_s[wcnt[12 + w] + __popc(mk1 & lmask)] = 384 + t;
    __syncthreads();        // list + weights visible (one block barrier)

    // =================== warp-autonomous mainloop ===========================
    const int ngroups = (cnt + 3) >> 2;        // 4-atom groups
    const int o       = 2 * lane;              // this lane's output pair
    const float RS32  = 0.17677669529663687f;  // 1/sqrt(32)
    float part0 = 0.f, part1 = 0.f;
    float* xwm = xw[w];
    float* swm = sw[w];

    for (int g = w; g < ngroups; g += NW) {
        // ---- gather 4 atoms x 32 features, [k][a], 1 LDG.128 per lane ----
        {
            int a = lane >> 3;             // atom slot 0..3
            int h = lane & 7;              // feature quarter (4 floats)
            int i = g * 4 + a;
            float4 r;
            if (i < cnt) {
                int id = b * NAT + list_s[i];
                r = __ldg((const float4*)(af + (size_t)id * DIN + h * 4));
            } else {
                r = make_float4(0.f, 0.f, 0.f, 0.f);
            }
            int kb = h * 4;
            xwm[(kb + 0) * 4 + a] = r.x;
            xwm[(kb + 1) * 4 + a] = r.y;
            xwm[(kb + 2) * 4 + a] = r.z;
            xwm[(kb + 3) * 4 + a] = r.w;
        }
        __syncwarp();

        // ---- stage 1: [4a x 32k x 64o] ----
        unsigned long long acc[2][2];      // [output j][atom pair p]
        acc[0][0] = acc[0][1] = acc[1][0] = acc[1][1] = 0ull;
        #pragma unroll
        for (int k = 0; k < IN0; k++) {
            ulonglong2 u0 = *(const ulonglong2*)&xwm[k * 4];   // broadcast
            float2 wf = *(const float2*)&WaN[k * HID + o];
            unsigned long long wd0 = pack2(wf.x), wd1 = pack2(wf.y);
            ffma2(acc[0][0], u0.x, wd0);
            ffma2(acc[0][1], u0.y, wd0);
            ffma2(acc[1][0], u0.x, wd1);
            ffma2(acc[1][1], u0.y, wd1);
        }
        // silu + store rows o, o+1 (4 atoms each): 2 STS.128
        #pragma unroll
        for (int j = 0; j < 2; j++) {
            float4 v;
            v.x = silu_f(lo32(acc[j][0]) * RS32);
            v.y = silu_f(hi32(acc[j][0]) * RS32);
            v.z = silu_f(lo32(acc[j][1]) * RS32);
            v.w = silu_f(hi32(acc[j][1]) * RS32);
            *(float4*)&swm[(o + j) * 4] = v;
        }
        __syncwarp();

        // ---- stage 2: [4a x 64k x 64o]; pad atoms are exact zeros ----
        unsigned long long acc2[2][2];
        acc2[0][0] = acc2[0][1] = acc2[1][0] = acc2[1][1] = 0ull;
        #pragma unroll
        for (int k = 0; k < HID; k++) {
            ulonglong2 u0 = *(const ulonglong2*)&swm[k * 4];   // broadcast
            float2 wf = *(const float2*)&WbN[k * HID + o];
            unsigned long long wd0 = pack2(wf.x), wd1 = pack2(wf.y);
            ffma2(acc2[0][0], u0.x, wd0);
            ffma2(acc2[0][1], u0.y, wd0);
            ffma2(acc2[1][0], u0.x, wd1);
            ffma2(acc2[1][1], u0.y, wd1);
        }
        part0 += silu_f(lo32(acc2[0][0]) * 0.125f)
               + silu_f(hi32(acc2[0][0]) * 0.125f)
               + silu_f(lo32(acc2[0][1]) * 0.125f)
               + silu_f(hi32(acc2[0][1]) * 0.125f);
        part1 += silu_f(lo32(acc2[1][0]) * 0.125f)
               + silu_f(hi32(acc2[1][0]) * 0.125f)
               + silu_f(lo32(acc2[1][1]) * 0.125f)
               + silu_f(hi32(acc2[1][1]) * 0.125f);
        __syncwarp();      // xw/sw reused next group
    }

    // ---- merge warp partials (idle warps contribute zeros) ----
    *(float2*)&pw[w * HID + o] = make_float2(part0, part1);
    __syncthreads();
    if (t < HID) {
        float s = 0.f;
        #pragma unroll
        for (int j = 0; j < NW; j++) s += pw[j * HID + t];
        red[t] = s;
    }
    __syncthreads();

    // ===== epilogue: out = (red @ Wout[cls]) / 8, 2-way k-split =====
    if (t < 2 * NOUT) {
        int oo = t & 127, half = t >> 7;
        const float* wp = Wo + (size_t)cls * HID * NOUT + half * 32 * NOUT + oo;
        float s = 0.0f;
        #pragma unroll
        for (int h = 0; h < 32; h++)
            s += red[half * 32 + h] * __ldg(&wp[h * NOUT]);
        psum[t] = s;
    }
    __syncthreads();
    if (t < NOUT)
        out[b * (NCLS * NOUT) + cls * NOUT + t] =
            0.125f * (psum[t] + psum[NOUT + t]);
}

// ---------------------------------------------------------------------------
extern "C" void kernel_launch(void* const* d_in, const int* in_sizes, int n_in,
                              void* d_out, int out_size) {
    const float* af      = (const float*)d_in[0];   // atom_features
    const float* W0      = (const float*)d_in[1];   // W0_0
    const float* W1      = (const float*)d_in[5];   // W1_0
    const float* Wo      = (const float*)d_in[9];   // Wout
    const int*   mapping = (const int*)  d_in[10];  // mlp_mapping
    float* out = (float*)d_out;

    fused_kernel<<<NBINS, NT>>>(af, W0, W1, Wo, mapping, out);
}